// round 10
// baseline (speedup 1.0000x reference)
#include <cuda_runtime.h>

#define H 50
#define BTOT 2048
#define TLEN 1024
#define BTILE 16
#define NTH 256
#define XCH 16
#define HP2 18   // hsplat row: 18 u64 = 144B (16B-aligned, bank shift 4 -> <=4-way store conflict)

__device__ float g_h1[BTOT * H];

typedef unsigned long long u64;

__device__ __forceinline__ u64 ffma2n(u64 a, u64 b, u64 c) {
    u64 d; asm("fma.rn.f32x2 %0, %1, %2, %3;" : "=l"(d) : "l"(a), "l"(b), "l"(c)); return d;
}
__device__ __forceinline__ void ffma2(u64 &d, u64 a, u64 b) {
    asm("fma.rn.f32x2 %0, %1, %2, %0;" : "+l"(d) : "l"(a), "l"(b));
}
__device__ __forceinline__ u64 pack2(float lo, float hi) {
    u64 r; asm("mov.b64 %0, {%1, %2};" : "=l"(r) : "f"(lo), "f"(hi)); return r;
}
__device__ __forceinline__ u64 splat2(float x) {
    u64 r; asm("mov.b64 %0, {%1, %1};" : "=l"(r) : "f"(x)); return r;
}
__device__ __forceinline__ void unpack2(u64 v, float &lo, float &hi) {
    asm("mov.b64 {%0, %1}, %2;" : "=f"(lo), "=f"(hi) : "l"(v));
}

// Single-MUFU activations.
__device__ __forceinline__ float tanh_f(float x) {
    float y; asm("tanh.approx.f32 %0, %1;" : "=f"(y) : "f"(x)); return y;
}
__device__ __forceinline__ float sigf(float x) {
    return fmaf(0.5f, tanh_f(0.5f * x), 0.5f);
}

// Dynamic smem layout (bytes from base)
#define OFF_WP0 0
#define OFF_WP1 20000
#define OFF_HS  40000                      // u64[2][H][HP2] = 14400 B
#define OFF_XS  (40000 + 14400)            // u64[XCH][16]  = 2048 B
#define SMEM1   (OFF_XS + 2048)

// Layer 1: persistent recurrence, warp-aligned batch groups + named barriers.
// NTH=256: group g = threads [64g, 64g+64) (2 warps), j = tid&63 (active j<50),
// handles batches 4g..4g+3. h/x pre-splatted as (v,v) u64 in shared so the
// k-loop is 6 LDS.64 + 8 FFMA2 with zero MOVs.
__global__ void __launch_bounds__(NTH) lstm1_kernel(
    const float* __restrict__ x,
    const float* __restrict__ Wih,
    const float* __restrict__ Whh,
    const float* __restrict__ bih,
    const float* __restrict__ bhh)
{
    extern __shared__ __align__(16) char sm[];
    float2* __restrict__ Wp0 = (float2*)(sm + OFF_WP0);   // [k*H+j] = (Wi,Wf)[j][k]
    float2* __restrict__ Wp1 = (float2*)(sm + OFF_WP1);   // [k*H+j] = (Wg,Wo)[j][k]
    u64*    __restrict__ hsp = (u64*)(sm + OFF_HS);       // [(buf*H+k)*HP2 + slot]
    u64*    __restrict__ xsp = (u64*)(sm + OFF_XS);       // [tc*16 + slot]

    const int tid = threadIdx.x;
    const int bg  = tid >> 6;        // group 0..3
    const int j   = tid & 63;        // hidden index, active if < 50
    const bool act = j < H;
    const int bbase = blockIdx.x * BTILE;
    const int sl = bg * 4;           // batch slot base

    // Prepack Whh gate-pairs into shared.
    for (int i = tid; i < 2 * H * H; i += NTH) {
        int p = i / (H * H);
        int rem = i - p * H * H;
        int k  = rem / H;
        int jj = rem - k * H;
        float lo = Whh[(p * 2 * H + jj) * H + k];
        float hi = Whh[(p * 2 * H + H + jj) * H + k];
        (p ? Wp1 : Wp0)[k * H + jj] = make_float2(lo, hi);
    }
    for (int i = tid; i < 2 * H * HP2; i += NTH)
        hsp[i] = 0ull;

    u64 biasp0 = 0, biasp1 = 0, wip0 = 0, wip1 = 0;
    if (act) {
        biasp0 = pack2(bih[j] + bhh[j],                 bih[H + j] + bhh[H + j]);
        biasp1 = pack2(bih[2 * H + j] + bhh[2 * H + j], bih[3 * H + j] + bhh[3 * H + j]);
        wip0 = pack2(Wih[j],         Wih[H + j]);
        wip1 = pack2(Wih[2 * H + j], Wih[3 * H + j]);
    }

    float c[4]  = {0.f, 0.f, 0.f, 0.f};
    float hv[4] = {0.f, 0.f, 0.f, 0.f};

    __syncthreads();

    const int li = j;  // 0..63 local index within group

    for (int t = 0; t < TLEN; t++) {
        if ((t & (XCH - 1)) == 0) {
            // group loads its own 4-batch x slice, pre-splatted
            int tc = li >> 2, s = li & 3;               // li in 0..63 = 16x4
            xsp[tc * 16 + sl + s] =
                splat2(x[(bbase + sl + s) * TLEN + t + tc]);
            asm volatile("bar.sync %0, 64;" :: "r"(bg + 1) : "memory");
        }
        const int buf = (t & 1) * H * HP2;
        const int nbuf = ((t & 1) ^ 1) * H * HP2;

        if (act) {
            const int xrow = (t & (XCH - 1)) * 16 + sl;
            u64 a00 = ffma2n(xsp[xrow],     wip0, biasp0);
            u64 a01 = ffma2n(xsp[xrow + 1], wip0, biasp0);
            u64 a02 = ffma2n(xsp[xrow + 2], wip0, biasp0);
            u64 a03 = ffma2n(xsp[xrow + 3], wip0, biasp0);
            u64 a10 = ffma2n(xsp[xrow],     wip1, biasp1);
            u64 a11 = ffma2n(xsp[xrow + 1], wip1, biasp1);
            u64 a12 = ffma2n(xsp[xrow + 2], wip1, biasp1);
            u64 a13 = ffma2n(xsp[xrow + 3], wip1, biasp1);

#pragma unroll
            for (int k = 0; k < H; k++) {
                const u64 w0 = *(const u64*)&Wp0[k * H + j];
                const u64 w1 = *(const u64*)&Wp1[k * H + j];
                const u64 hs0 = hsp[buf + k * HP2 + sl];
                const u64 hs1 = hsp[buf + k * HP2 + sl + 1];
                const u64 hs2 = hsp[buf + k * HP2 + sl + 2];
                const u64 hs3 = hsp[buf + k * HP2 + sl + 3];
                ffma2(a00, hs0, w0); ffma2(a10, hs0, w1);
                ffma2(a01, hs1, w0); ffma2(a11, hs1, w1);
                ffma2(a02, hs2, w0); ffma2(a12, hs2, w1);
                ffma2(a03, hs3, w0); ffma2(a13, hs3, w1);
            }

            u64 A0[4] = {a00, a01, a02, a03};
            u64 A1[4] = {a10, a11, a12, a13};
#pragma unroll
            for (int r = 0; r < 4; r++) {
                float ip, fp, gp, op;
                unpack2(A0[r], ip, fp);
                unpack2(A1[r], gp, op);
                const float ig = sigf(ip);
                const float fg = sigf(fp);
                const float gg = tanh_f(gp);
                const float og = sigf(op);
                c[r]  = fmaf(fg, c[r], ig * gg);
                hv[r] = og * tanh_f(c[r]);
            }
            // store pre-splatted h: (h0,h0,h1,h1) and (h2,h2,h3,h3)
            *(float4*)&hsp[nbuf + j * HP2 + sl] =
                make_float4(hv[0], hv[0], hv[1], hv[1]);
            *(float4*)&hsp[nbuf + j * HP2 + sl + 2] =
                make_float4(hv[2], hv[2], hv[3], hv[3]);
        }
        asm volatile("bar.sync %0, 64;" :: "r"(bg + 1) : "memory");
    }

    if (act) {
#pragma unroll
        for (int r = 0; r < 4; r++)
            g_h1[(bbase + sl + r) * H + j] = hv[r];
    }
}

#define NTH2 256

__global__ void __launch_bounds__(NTH2) lstm2_fc_kernel(
    const float* __restrict__ W2ih,
    const float* __restrict__ b2ih,
    const float* __restrict__ b2hh,
    const float* __restrict__ fcW,
    const float* __restrict__ fcb,
    float* __restrict__ out)
{
    __shared__ __align__(16) float Wsh[H][4 * H];
    __shared__ __align__(16) float h1sh[H][BTILE];
    __shared__ float h2sh[BTILE][H];

    const int tid = threadIdx.x;
    const int j = tid & 63;
    const int bg = tid >> 6;
    const int bbase = blockIdx.x * BTILE;
    const int bloc = bg * 4;

    for (int i = tid; i < 4 * H * H; i += NTH2) {
        int g = i / H, k = i - g * H;
        Wsh[k][g] = W2ih[i];
    }
    for (int i = tid; i < H * BTILE; i += NTH2) {
        int k = i >> 4, bl = i & 15;
        h1sh[k][bl] = g_h1[(bbase + bl) * H + k];
    }
    __syncthreads();

    if (j < H) {
        const float bias0 = b2ih[j]         + b2hh[j];
        const float bias2 = b2ih[2 * H + j] + b2hh[2 * H + j];
        const float bias3 = b2ih[3 * H + j] + b2hh[3 * H + j];
        float a0[4], a2[4], a3[4];
#pragma unroll
        for (int r = 0; r < 4; r++) { a0[r] = bias0; a2[r] = bias2; a3[r] = bias3; }
#pragma unroll
        for (int k = 0; k < H; k++) {
            const float w0 = Wsh[k][j];
            const float w2 = Wsh[k][2 * H + j];
            const float w3 = Wsh[k][3 * H + j];
            const float4 h4 = *(const float4*)&h1sh[k][bloc];
            const float hr[4] = {h4.x, h4.y, h4.z, h4.w};
#pragma unroll
            for (int r = 0; r < 4; r++) {
                a0[r] = fmaf(hr[r], w0, a0[r]);
                a2[r] = fmaf(hr[r], w2, a2[r]);
                a3[r] = fmaf(hr[r], w3, a3[r]);
            }
        }
#pragma unroll
        for (int r = 0; r < 4; r++) {
            const float ig = sigf(a0[r]);           // f-gate unused: c0 = 0
            const float gg = tanh_f(a2[r]);
            const float og = sigf(a3[r]);
            const float cc = ig * gg;
            h2sh[bloc + r][j] = og * tanh_f(cc);
        }
    }
    __syncthreads();

    if (tid < BTILE) {
        float s = fcb[0];
#pragma unroll
        for (int k = 0; k < H; k++)
            s = fmaf(h2sh[tid][k], fcW[k], s);
        out[bbase + tid] = s;
    }
}

extern "C" void kernel_launch(void* const* d_in, const int* in_sizes, int n_in,
                              void* d_out, int out_size)
{
    const float* x     = (const float*)d_in[0];
    const float* w1ih  = (const float*)d_in[1];
    const float* w1hh  = (const float*)d_in[2];
    const float* b1ih  = (const float*)d_in[3];
    const float* b1hh  = (const float*)d_in[4];
    const float* w2ih  = (const float*)d_in[5];
    // d_in[6] = lstm2_Whh: unused (layer-2 initial state is zero)
    const float* b2ih  = (const float*)d_in[7];
    const float* b2hh  = (const float*)d_in[8];
    const float* fcW   = (const float*)d_in[9];
    const float* fcb   = (const float*)d_in[10];
    float* out = (float*)d_out;

    // idempotent; host-side, legal during graph capture
    cudaFuncSetAttribute(lstm1_kernel,
                         cudaFuncAttributeMaxDynamicSharedMemorySize, SMEM1);

    lstm1_kernel<<<BTOT / BTILE, NTH, SMEM1>>>(x, w1ih, w1hh, b1ih, b1hh);
    lstm2_fc_kernel<<<BTOT / BTILE, NTH2>>>(w2ih, b2ih, b2hh, fcW, fcb, out);
}

// round 11
// speedup vs baseline: 1.3296x; 1.3296x over previous
#include <cuda_runtime.h>

#define H 50
#define BTOT 2048
#define TLEN 1024
#define BTILE 16
#define NTH 200
#define XCH 16
#define GP 5    // hsh row: 5 float4 = 80B (odd*16B) -> at most 4-way store conflict

__device__ float g_h1[BTOT * H];

typedef unsigned long long u64;

__device__ __forceinline__ u64 ffma2n(u64 a, u64 b, u64 c) {
    u64 d; asm("fma.rn.f32x2 %0, %1, %2, %3;" : "=l"(d) : "l"(a), "l"(b), "l"(c)); return d;
}
__device__ __forceinline__ void ffma2(u64 &d, u64 a, u64 b) {
    asm("fma.rn.f32x2 %0, %1, %2, %0;" : "+l"(d) : "l"(a), "l"(b));
}
__device__ __forceinline__ u64 splat2(float x) {
    u64 r; asm("mov.b64 %0, {%1, %1};" : "=l"(r) : "f"(x)); return r;
}
__device__ __forceinline__ void unpack2(u64 v, float &lo, float &hi) {
    asm("mov.b64 {%0, %1}, %2;" : "=f"(lo), "=f"(hi) : "l"(v));
}

// Single-MUFU activations.
__device__ __forceinline__ float tanh_f(float x) {
    float y; asm("tanh.approx.f32 %0, %1;" : "=f"(y) : "f"(x)); return y;
}
__device__ __forceinline__ float sigf(float x) {
    return fmaf(0.5f, tanh_f(0.5f * x), 0.5f);
}

// Layer 1: persistent recurrence. 200 threads = 4 batch-groups x 50 hidden.
// Accumulators packed across BATCH pairs: aG01=(pre_G[b0],pre_G[b1]) etc.
//  - h operand: natural (h0,h1)/(h2,h3) pairs -> broadcast LDS.64, no splats.
//  - weights: one LDS.128 (Wi,Wf,Wg,Wo) + 4 register splats per k.
// Inner k: 1 LDS.128 + 2 LDS.64 + 4 MOV + 8 FFMA2 = 15 instr.
__global__ void __launch_bounds__(NTH) lstm1_kernel(
    const float* __restrict__ x,
    const float* __restrict__ Wih,
    const float* __restrict__ Whh,
    const float* __restrict__ bih,
    const float* __restrict__ bhh)
{
    __shared__ __align__(16) float4 Wq[H][H];        // [k][j] = (Wi,Wf,Wg,Wo)[j][k]  40000B
    __shared__ __align__(16) float4 hsh[2][H][GP];   // [buf][k][group] = (h0..h3)     8000B
    __shared__ __align__(16) float  xsh[XCH][16];    // x chunk                        1024B

    const int tid = threadIdx.x;
    const int bg = tid / H;          // 0..3
    const int j  = tid - bg * H;     // 0..49, all threads active
    const int bbase = blockIdx.x * BTILE;

    // Prepack Whh gate quads: Wq[k][j] = 4 gate rows at column k
    for (int i = tid; i < H * H; i += NTH) {
        int k = i / H, jj = i - k * H;
        Wq[k][jj] = make_float4(Whh[jj * H + k],
                                Whh[(H + jj) * H + k],
                                Whh[(2 * H + jj) * H + k],
                                Whh[(3 * H + jj) * H + k]);
    }
    for (int i = tid; i < 2 * H * GP; i += NTH)
        ((float4*)hsh)[i] = make_float4(0.f, 0.f, 0.f, 0.f);

    // Per-thread splatted constants (same value for both batches of a pair)
    const u64 bI = splat2(bih[j]         + bhh[j]);
    const u64 bF = splat2(bih[H + j]     + bhh[H + j]);
    const u64 bG = splat2(bih[2 * H + j] + bhh[2 * H + j]);
    const u64 bO = splat2(bih[3 * H + j] + bhh[3 * H + j]);
    const u64 wiI = splat2(Wih[j]);
    const u64 wiF = splat2(Wih[H + j]);
    const u64 wiG = splat2(Wih[2 * H + j]);
    const u64 wiO = splat2(Wih[3 * H + j]);

    float c[4]  = {0.f, 0.f, 0.f, 0.f};
    float hv[4] = {0.f, 0.f, 0.f, 0.f};

    __syncthreads();

    for (int t = 0; t < TLEN; t++) {
        if ((t & (XCH - 1)) == 0) {
            // previous end-of-step barrier guarantees old xsh reads are done
            for (int i = tid; i < XCH * BTILE; i += NTH) {
                int tc = i >> 4, bl = i & 15;
                xsh[tc][bl] = x[(bbase + bl) * TLEN + t + tc];
            }
            __syncthreads();
        }
        const int buf = t & 1;

        // x pairs for this group's 4 batches
        const u64* xp = (const u64*)&xsh[t & (XCH - 1)][bg * 4];
        const u64 x01 = xp[0], x23 = xp[1];

        u64 aI01 = ffma2n(x01, wiI, bI), aI23 = ffma2n(x23, wiI, bI);
        u64 aF01 = ffma2n(x01, wiF, bF), aF23 = ffma2n(x23, wiF, bF);
        u64 aG01 = ffma2n(x01, wiG, bG), aG23 = ffma2n(x23, wiG, bG);
        u64 aO01 = ffma2n(x01, wiO, bO), aO23 = ffma2n(x23, wiO, bO);

#pragma unroll
        for (int k = 0; k < H; k++) {
            const float4 w = Wq[k][j];                       // LDS.128
            const u64* hp = (const u64*)&hsh[buf][k][bg];    // broadcast
            const u64 h01 = hp[0], h23 = hp[1];
            const u64 wI = splat2(w.x), wF = splat2(w.y);
            const u64 wG = splat2(w.z), wO = splat2(w.w);
            ffma2(aI01, h01, wI); ffma2(aI23, h23, wI);
            ffma2(aF01, h01, wF); ffma2(aF23, h23, wF);
            ffma2(aG01, h01, wG); ffma2(aG23, h23, wG);
            ffma2(aO01, h01, wO); ffma2(aO23, h23, wO);
        }

        float ip[4], fp[4], gp[4], op[4];
        unpack2(aI01, ip[0], ip[1]); unpack2(aI23, ip[2], ip[3]);
        unpack2(aF01, fp[0], fp[1]); unpack2(aF23, fp[2], fp[3]);
        unpack2(aG01, gp[0], gp[1]); unpack2(aG23, gp[2], gp[3]);
        unpack2(aO01, op[0], op[1]); unpack2(aO23, op[2], op[3]);
#pragma unroll
        for (int r = 0; r < 4; r++) {
            const float ig = sigf(ip[r]);
            const float fg = sigf(fp[r]);
            const float gg = tanh_f(gp[r]);
            const float og = sigf(op[r]);
            c[r]  = fmaf(fg, c[r], ig * gg);
            hv[r] = og * tanh_f(c[r]);
        }
        hsh[buf ^ 1][j][bg] = make_float4(hv[0], hv[1], hv[2], hv[3]);
        __syncthreads();
    }

#pragma unroll
    for (int r = 0; r < 4; r++)
        g_h1[(bbase + bg * 4 + r) * H + j] = hv[r];
}

#define NTH2 256

__global__ void __launch_bounds__(NTH2) lstm2_fc_kernel(
    const float* __restrict__ W2ih,
    const float* __restrict__ b2ih,
    const float* __restrict__ b2hh,
    const float* __restrict__ fcW,
    const float* __restrict__ fcb,
    float* __restrict__ out)
{
    __shared__ __align__(16) float Wsh[H][4 * H];
    __shared__ __align__(16) float h1sh[H][BTILE];
    __shared__ float h2sh[BTILE][H];

    const int tid = threadIdx.x;
    const int j = tid & 63;
    const int bg = tid >> 6;
    const int bbase = blockIdx.x * BTILE;
    const int bloc = bg * 4;

    for (int i = tid; i < 4 * H * H; i += NTH2) {
        int g = i / H, k = i - g * H;
        Wsh[k][g] = W2ih[i];
    }
    for (int i = tid; i < H * BTILE; i += NTH2) {
        int k = i >> 4, bl = i & 15;
        h1sh[k][bl] = g_h1[(bbase + bl) * H + k];
    }
    __syncthreads();

    if (j < H) {
        const float bias0 = b2ih[j]         + b2hh[j];
        const float bias2 = b2ih[2 * H + j] + b2hh[2 * H + j];
        const float bias3 = b2ih[3 * H + j] + b2hh[3 * H + j];
        float a0[4], a2[4], a3[4];
#pragma unroll
        for (int r = 0; r < 4; r++) { a0[r] = bias0; a2[r] = bias2; a3[r] = bias3; }
#pragma unroll
        for (int k = 0; k < H; k++) {
            const float w0 = Wsh[k][j];
            const float w2 = Wsh[k][2 * H + j];
            const float w3 = Wsh[k][3 * H + j];
            const float4 h4 = *(const float4*)&h1sh[k][bloc];
            const float hr[4] = {h4.x, h4.y, h4.z, h4.w};
#pragma unroll
            for (int r = 0; r < 4; r++) {
                a0[r] = fmaf(hr[r], w0, a0[r]);
                a2[r] = fmaf(hr[r], w2, a2[r]);
                a3[r] = fmaf(hr[r], w3, a3[r]);
            }
        }
#pragma unroll
        for (int r = 0; r < 4; r++) {
            const float ig = sigf(a0[r]);           // f-gate unused: c0 = 0
            const float gg = tanh_f(a2[r]);
            const float og = sigf(a3[r]);
            const float cc = ig * gg;
            h2sh[bloc + r][j] = og * tanh_f(cc);
        }
    }
    __syncthreads();

    if (tid < BTILE) {
        float s = fcb[0];
#pragma unroll
        for (int k = 0; k < H; k++)
            s = fmaf(h2sh[tid][k], fcW[k], s);
        out[bbase + tid] = s;
    }
}

extern "C" void kernel_launch(void* const* d_in, const int* in_sizes, int n_in,
                              void* d_out, int out_size)
{
    const float* x     = (const float*)d_in[0];
    const float* w1ih  = (const float*)d_in[1];
    const float* w1hh  = (const float*)d_in[2];
    const float* b1ih  = (const float*)d_in[3];
    const float* b1hh  = (const float*)d_in[4];
    const float* w2ih  = (const float*)d_in[5];
    // d_in[6] = lstm2_Whh: unused (layer-2 initial state is zero)
    const float* b2ih  = (const float*)d_in[7];
    const float* b2hh  = (const float*)d_in[8];
    const float* fcW   = (const float*)d_in[9];
    const float* fcb   = (const float*)d_in[10];
    float* out = (float*)d_out;

    lstm1_kernel<<<BTOT / BTILE, NTH>>>(x, w1ih, w1hh, b1ih, b1hh);
    lstm2_fc_kernel<<<BTOT / BTILE, NTH2>>>(w2ih, b2ih, b2hh, fcW, fcb, out);
}